// round 5
// baseline (speedup 1.0000x reference)
#include <cuda_runtime.h>
#include <math.h>

// Problem constants
#define F_DIM   512
#define B_DIM   512
#define L_DIM   256
#define C_DIM   128

#define GRID_BLOCKS 128
#define THREADS     256
#define FT   16      // f rows per block
#define BT   128     // batch cols per block
#define KCH  64      // k-chunk rows in smem
#define WST  64      // Wsh row stride in floats

// Persistent device state (allowed: __device__ globals, no allocation)
__device__ float g_h[2][F_DIM * B_DIM];
__device__ unsigned g_bar_count;
__device__ volatile unsigned g_bar_sense;

typedef unsigned long long u64;

__device__ __forceinline__ void fma2(u64 &d, u64 a, u64 b) {
    asm("fma.rn.f32x2 %0, %1, %2, %0;" : "+l"(d) : "l"(a), "l"(b));
}
__device__ __forceinline__ float2 unpack2(u64 v) {
    float2 f; asm("mov.b64 {%0, %1}, %2;" : "=f"(f.x), "=f"(f.y) : "l"(v)); return f;
}

// Accurate activations that do NOT degrade under fast-math builds.
// exp2f lowers to ex2.approx.f32 (~2^-22 rel err) on all build modes.
__device__ __forceinline__ float sigm(float x) {
    const float e = exp2f(-1.4426950408889634f * x);
    return 1.0f / (1.0f + e);
}
__device__ __forceinline__ float tanh_acc(float x) {
    const float xc = fminf(fmaxf(x, -9.0f), 9.0f);   // tanh(|x|>9) == 1.0f in fp32
    const float e = exp2f(2.8853900817779268f * xc); // exp(2x)
    return (e - 1.0f) / (e + 1.0f);
}

// Grid-wide sense-reversing barrier; initial sense read from global at kernel
// start so the odd per-launch barrier count stays replay-deterministic.
__device__ __forceinline__ void gsync(unsigned* s_sense) {
    __threadfence();          // release this thread's prior global stores
    __syncthreads();
    if (threadIdx.x == 0) {
        unsigned ns = *s_sense ^ 1u;
        *s_sense = ns;
        unsigned old = atomicAdd(&g_bar_count, 1u);
        if (old == GRID_BLOCKS - 1u) {
            g_bar_count = 0u;
            __threadfence();
            g_bar_sense = ns;
        } else {
            while (g_bar_sense != ns) { }
        }
    }
    __syncthreads();
    __threadfence();          // acquire: order subsequent loads
    __syncthreads();
}

__global__ void __launch_bounds__(THREADS, 1)
lstm_persist_kernel(const float* __restrict__ x,
                    const float* __restrict__ w_gx, const float* __restrict__ w_gh,
                    const float* __restrict__ w_ix, const float* __restrict__ w_ih,
                    const float* __restrict__ w_fx, const float* __restrict__ w_fh,
                    const float* __restrict__ w_ox, const float* __restrict__ w_oh,
                    const float* __restrict__ w_ph,
                    const float* __restrict__ b_g, const float* __restrict__ b_i,
                    const float* __restrict__ b_f, const float* __restrict__ b_o,
                    const float* __restrict__ b_p,
                    float* __restrict__ out)
{
    extern __shared__ float smem[];
    float* Wsh = smem;                  // [512][WST] transposed weights: Wsh[k][fl*4+gate]
    float* hs2 = Wsh + F_DIM * WST;     // [KCH][2*BT] h chunk, each value DUPLICATED
    float* sx  = hs2 + KCH * 2 * BT;    // [BT] x slice for this step
    float* swx = sx + BT;               // [64] per-row w_*x value

    const int tid   = threadIdx.x;
    const int bid   = blockIdx.x;
    const int ftile = bid & 31;         // 32 f-tiles of 16 rows
    const int btile = bid >> 5;         // 4 b-tiles of 128 cols
    const int rg    = tid >> 5;         // 0..7 : owns gate-rows rg*8 .. rg*8+7
    const int cg    = tid & 31;         // 0..31: owns cols cg*4 .. cg*4+3
    const int b0    = btile * BT;
    const int cbase = cg << 2;

    __shared__ unsigned s_sense;
    if (tid == 0) s_sense = g_bar_sense;   // safe: sense can't change until this block arrives

    // ---- Load stationary weights, transposed: row r = fl*4 + gate ----
    {
        const float* Wh[4] = {w_gh, w_ih, w_fh, w_oh};
        #pragma unroll 1
        for (int r = 0; r < 64; ++r) {
            const int fl = r >> 2, gt = r & 3;
            const float2 v = ((const float2*)(Wh[gt] + (ftile * FT + fl) * F_DIM))[tid];
            Wsh[(2 * tid    ) * WST + r] = v.x;
            Wsh[(2 * tid + 1) * WST + r] = v.y;
        }
        if (tid < 64) {
            const int fl = tid >> 2, gt = tid & 3, f = ftile * FT + fl;
            const float* Wx[4] = {w_gx, w_ix, w_fx, w_ox};
            swx[tid] = Wx[gt][f];
        }
    }

    // Reference semantics: gate biases (F,)==(B,) broadcast along the TRAILING
    // (batch) axis -> bias indexed by BATCH column, not feature row.
    float bgc[4], bic[4], bfc[4], boc[4];
    #pragma unroll
    for (int ci = 0; ci < 4; ++ci) {
        const int b = b0 + cbase + ci;
        bgc[ci] = b_g[b];
        bic[ci] = b_i[b];
        bfc[ci] = b_f[b];
        boc[ci] = b_o[b];
    }

    // ---- Zero our tile of h buffer 0 (h0 = 0) ----
    for (int q = tid; q < FT * BT; q += THREADS) {
        const int fl = q >> 7, c = q & 127;
        g_h[0][(ftile * FT + fl) * B_DIM + b0 + c] = 0.0f;
    }
    gsync(&s_sense);

    // ---- Recurrence state ----
    // acc[p][c]: f32x2 pair over ROWS: lane0 = gate-row rg*8+2p, lane1 = +2p+1,
    // batch col = cbase + c.  p=0: (g,i) of fl0; p=1: (f,o) of fl0; p=2/3: fl1.
    u64   acc[4][4];
    float cst[8];         // c state: 2 f-rows x 4 cols, cst[fl*4+c]
    #pragma unroll
    for (int p = 0; p < 4; ++p)
        #pragma unroll
        for (int c = 0; c < 4; ++c) acc[p][c] = 0ull;
    #pragma unroll
    for (int i = 0; i < 8; ++i) cst[i] = 0.0f;

    for (int t = 0; t < L_DIM; ++t) {
        const float* __restrict__ hsrc = g_h[t & 1];
        float* __restrict__ hdst = g_h[(t & 1) ^ 1];

        // prefetch chunk 0 into registers
        float4 pf[8];
        #pragma unroll
        for (int q = 0; q < 8; ++q) {
            const int idx = tid + (q << 8);
            const int kk = idx >> 5, c4 = idx & 31;
            pf[q] = *(const float4*)&hsrc[kk * B_DIM + b0 + (c4 << 2)];
        }
        if (tid < BT) sx[tid] = x[(b0 + tid) * L_DIM + t];

        for (int kc = 0; kc < 8; ++kc) {
            __syncthreads();                       // previous chunk fully consumed
            // store chunk DUPLICATED: hs2[kk][2c] = hs2[kk][2c+1] = h[kk][c]
            #pragma unroll
            for (int q = 0; q < 8; ++q) {
                const int idx = tid + (q << 8);
                const float4 v = pf[q];
                float4* dst = (float4*)hs2 + (idx << 1);
                dst[0] = make_float4(v.x, v.x, v.y, v.y);
                dst[1] = make_float4(v.z, v.z, v.w, v.w);
            }
            if (kc < 7) {                           // prefetch next chunk (overlaps compute)
                #pragma unroll
                for (int q = 0; q < 8; ++q) {
                    const int idx = tid + (q << 8);
                    const int kk = idx >> 5, c4 = idx & 31;
                    pf[q] = *(const float4*)&hsrc[((kc + 1) * KCH + kk) * B_DIM + b0 + (c4 << 2)];
                }
            }
            __syncthreads();

            const float* wbase = Wsh + (kc * KCH) * WST + (rg << 3);
            const float* hbase = hs2 + (cbase << 1);
            #pragma unroll 4
            for (int kk = 0; kk < KCH; ++kk) {
                // weights: 8 consecutive rows -> 4 ready-made f32x2 pairs (broadcast LDS)
                const u64* wp = (const u64*)(wbase + (kk << 6));
                const u64 w0 = wp[0], w1 = wp[1], w2 = wp[2], w3 = wp[3];
                // h: duplicated pairs (h_c, h_c)
                const u64* hp = (const u64*)(hbase + (kk << 8));
                const u64 h0 = hp[0], h1 = hp[1], h2 = hp[2], h3 = hp[3];
                fma2(acc[0][0], w0, h0); fma2(acc[0][1], w0, h1);
                fma2(acc[0][2], w0, h2); fma2(acc[0][3], w0, h3);
                fma2(acc[1][0], w1, h0); fma2(acc[1][1], w1, h1);
                fma2(acc[1][2], w1, h2); fma2(acc[1][3], w1, h3);
                fma2(acc[2][0], w2, h0); fma2(acc[2][1], w2, h1);
                fma2(acc[2][2], w2, h2); fma2(acc[2][3], w2, h3);
                fma2(acc[3][0], w3, h0); fma2(acc[3][1], w3, h1);
                fma2(acc[3][2], w3, h2); fma2(acc[3][3], w3, h3);
            }
        }

        // ---- Gates + state update for owned (2 f-rows x 4 cols) ----
        const float xv[4] = {sx[cbase + 0], sx[cbase + 1], sx[cbase + 2], sx[cbase + 3]};
        #pragma unroll
        for (int fl2 = 0; fl2 < 2; ++fl2) {
            const int r0 = (rg << 3) + (fl2 << 2);
            const int fl = (rg << 1) + fl2;
            float4 hv;
            float* hvp = (float*)&hv;
            #pragma unroll
            for (int ci = 0; ci < 4; ++ci) {
                const float2 gi = unpack2(acc[(fl2 << 1) + 0][ci]);  // (g, i)
                const float2 fo = unpack2(acc[(fl2 << 1) + 1][ci]);  // (f, o)
                const float pg  = gi.x + swx[r0 + 0] * xv[ci] + bgc[ci];
                const float pi  = gi.y + swx[r0 + 1] * xv[ci] + bic[ci];
                const float pff = fo.x + swx[r0 + 2] * xv[ci] + bfc[ci];
                const float po  = fo.y + swx[r0 + 3] * xv[ci] + boc[ci];
                const float gg = tanh_acc(pg);
                const float si = sigm(pi);
                const float sf = sigm(pff);
                const float so = sigm(po);
                const float cn = gg * si + cst[(fl2 << 2) + ci] * sf;
                cst[(fl2 << 2) + ci] = cn;
                hvp[ci] = tanh_acc(cn) * so;
            }
            *(float4*)&hdst[(ftile * FT + fl) * B_DIM + b0 + cbase] = hv;
        }
        #pragma unroll
        for (int p = 0; p < 4; ++p)
            #pragma unroll
            for (int c = 0; c < 4; ++c) acc[p][c] = 0ull;
        gsync(&s_sense);
    }

    // ---- Projection: p = h^T @ w_ph + b_p ; final h is in g_h[0] (L even) ----
    {
        const float* __restrict__ hfin = g_h[0];
        const int c = tid & 127;
        const int brow = (bid << 2) + ((tid >> 7) << 1);  // block owns 4 batch rows
        float a0 = 0.0f, a1 = 0.0f;
        #pragma unroll 4
        for (int f = 0; f < F_DIM; ++f) {
            const float w = w_ph[f * C_DIM + c];
            a0 += hfin[f * B_DIM + brow] * w;
            a1 += hfin[f * B_DIM + brow + 1] * w;
        }
        const float bp = b_p[c];
        out[brow * C_DIM + c]       = a0 + bp;
        out[(brow + 1) * C_DIM + c] = a1 + bp;
    }
}

extern "C" void kernel_launch(void* const* d_in, const int* in_sizes, int n_in,
                              void* d_out, int out_size)
{
    (void)in_sizes; (void)n_in; (void)out_size;
    const float* x    = (const float*)d_in[0];
    const float* w_gx = (const float*)d_in[1];
    const float* w_gh = (const float*)d_in[2];
    const float* w_ix = (const float*)d_in[3];
    const float* w_ih = (const float*)d_in[4];
    const float* w_fx = (const float*)d_in[5];
    const float* w_fh = (const float*)d_in[6];
    const float* w_ox = (const float*)d_in[7];
    const float* w_oh = (const float*)d_in[8];
    const float* w_ph = (const float*)d_in[9];
    const float* b_g  = (const float*)d_in[10];
    const float* b_i  = (const float*)d_in[11];
    const float* b_f  = (const float*)d_in[12];
    const float* b_o  = (const float*)d_in[13];
    const float* b_p  = (const float*)d_in[14];
    float* out = (float*)d_out;

    const size_t smem_bytes = (size_t)(F_DIM * WST + KCH * 2 * BT + BT + 64) * sizeof(float);
    cudaFuncSetAttribute(lstm_persist_kernel,
                         cudaFuncAttributeMaxDynamicSharedMemorySize, (int)smem_bytes);

    lstm_persist_kernel<<<GRID_BLOCKS, THREADS, smem_bytes>>>(
        x, w_gx, w_gh, w_ix, w_ih, w_fx, w_fh, w_ox, w_oh, w_ph,
        b_g, b_i, b_f, b_o, b_p, out);
}

// round 6
// speedup vs baseline: 1.6694x; 1.6694x over previous
#include <cuda_runtime.h>
#include <math.h>

// Problem constants
#define F_DIM   512
#define B_DIM   512
#define L_DIM   256
#define C_DIM   128

#define GRID_BLOCKS 128
#define THREADS     256
#define FT   16      // f rows per block
#define BT   128     // batch cols per block
#define KCH  64      // k-chunk rows in smem
#define WST  64      // Wsh row stride in floats

// Persistent device state (allowed: __device__ globals, no allocation)
__device__ float g_h[2][F_DIM * B_DIM];
__device__ unsigned g_bar_count;
__device__ volatile unsigned g_bar_sense;

typedef unsigned long long u64;

__device__ __forceinline__ u64 pack2(float w) {
    u64 r; asm("mov.b64 %0, {%1, %1};" : "=l"(r) : "f"(w)); return r;
}
__device__ __forceinline__ void fma2(u64 &d, u64 a, u64 b) {
    asm("fma.rn.f32x2 %0, %1, %2, %0;" : "+l"(d) : "l"(a), "l"(b));
}
__device__ __forceinline__ float2 unpack2(u64 v) {
    float2 f; asm("mov.b64 {%0, %1}, %2;" : "=f"(f.x), "=f"(f.y) : "l"(v)); return f;
}

// Accurate activations that do NOT degrade under fast-math builds.
__device__ __forceinline__ float sigm(float x) {
    const float e = exp2f(-1.4426950408889634f * x);
    return 1.0f / (1.0f + e);
}
__device__ __forceinline__ float tanh_acc(float x) {
    const float xc = fminf(fmaxf(x, -9.0f), 9.0f);   // tanh(|x|>9) == 1.0f in fp32
    const float e = exp2f(2.8853900817779268f * xc); // exp(2x)
    return (e - 1.0f) / (e + 1.0f);
}

// Grid-wide sense-reversing barrier. The post-wait __threadfence is
// load-bearing: it invalidates L1D so next-step h reads see peer-SM stores.
__device__ __forceinline__ void gsync(unsigned* s_sense) {
    __threadfence();          // release this thread's prior global stores
    __syncthreads();
    if (threadIdx.x == 0) {
        unsigned ns = *s_sense ^ 1u;
        *s_sense = ns;
        unsigned old = atomicAdd(&g_bar_count, 1u);
        if (old == GRID_BLOCKS - 1u) {
            g_bar_count = 0u;
            __threadfence();
            g_bar_sense = ns;
        } else {
            while (g_bar_sense != ns) { }
        }
    }
    __syncthreads();
    __threadfence();          // acquire + L1 invalidate
    __syncthreads();
}

__global__ void __launch_bounds__(THREADS, 1)
lstm_persist_kernel(const float* __restrict__ x,
                    const float* __restrict__ w_gx, const float* __restrict__ w_gh,
                    const float* __restrict__ w_ix, const float* __restrict__ w_ih,
                    const float* __restrict__ w_fx, const float* __restrict__ w_fh,
                    const float* __restrict__ w_ox, const float* __restrict__ w_oh,
                    const float* __restrict__ w_ph,
                    const float* __restrict__ b_g, const float* __restrict__ b_i,
                    const float* __restrict__ b_f, const float* __restrict__ b_o,
                    const float* __restrict__ b_p,
                    float* __restrict__ out)
{
    extern __shared__ float smem[];
    float* Wsh = smem;                  // [512][WST] transposed weights: Wsh[k][fl*4+gate]
    float* hs  = Wsh + F_DIM * WST;     // [KCH][BT] h chunk (NOT duplicated)
    float* sx  = hs + KCH * BT;         // [BT] x slice for this step
    float* swx = sx + BT;               // [64] per-row w_*x value

    const int tid   = threadIdx.x;
    const int bid   = blockIdx.x;
    const int ftile = bid & 31;         // 32 f-tiles of 16 rows
    const int btile = bid >> 5;         // 4 b-tiles of 128 cols
    const int rg    = tid >> 5;         // 0..7 : owns gate-rows rg*8 .. rg*8+7
    const int cg    = tid & 31;         // 0..31: owns cols cg*4 .. cg*4+3
    const int b0    = btile * BT;
    const int cbase = cg << 2;

    __shared__ unsigned s_sense;
    if (tid == 0) s_sense = g_bar_sense;   // safe: sense can't change until this block arrives

    // ---- Load stationary weights, transposed: row r = fl*4 + gate ----
    {
        const float* Wh[4] = {w_gh, w_ih, w_fh, w_oh};
        #pragma unroll 1
        for (int r = 0; r < 64; ++r) {
            const int fl = r >> 2, gt = r & 3;
            const float2 v = ((const float2*)(Wh[gt] + (ftile * FT + fl) * F_DIM))[tid];
            Wsh[(2 * tid    ) * WST + r] = v.x;
            Wsh[(2 * tid + 1) * WST + r] = v.y;
        }
        if (tid < 64) {
            const int fl = tid >> 2, gt = tid & 3, f = ftile * FT + fl;
            const float* Wx[4] = {w_gx, w_ix, w_fx, w_ox};
            swx[tid] = Wx[gt][f];
        }
    }

    // Reference semantics: gate biases (F,)==(B,) broadcast along the TRAILING
    // (batch) axis -> bias indexed by BATCH column, not feature row.
    float bgc[4], bic[4], bfc[4], boc[4];
    #pragma unroll
    for (int ci = 0; ci < 4; ++ci) {
        const int b = b0 + cbase + ci;
        bgc[ci] = b_g[b];
        bic[ci] = b_i[b];
        bfc[ci] = b_f[b];
        boc[ci] = b_o[b];
    }

    // ---- Zero our tile of h buffer 0 (h0 = 0) ----
    for (int q = tid; q < FT * BT; q += THREADS) {
        const int fl = q >> 7, c = q & 127;
        g_h[0][(ftile * FT + fl) * B_DIM + b0 + c] = 0.0f;
    }
    gsync(&s_sense);

    // ---- Recurrence state ----
    // acc[p][c]: f32x2 over ROWS: lanes = gate-rows (rg*8+2p, rg*8+2p+1),
    // batch col = cbase+c.  p=0: (g,i) fl0; p=1: (f,o) fl0; p=2,3: fl1.
    u64   acc[4][4];
    float cst[8];         // c state: 2 f-rows x 4 cols, cst[fl*4+c]
    #pragma unroll
    for (int p = 0; p < 4; ++p)
        #pragma unroll
        for (int c = 0; c < 4; ++c) acc[p][c] = 0ull;
    #pragma unroll
    for (int i = 0; i < 8; ++i) cst[i] = 0.0f;

    for (int t = 0; t < L_DIM; ++t) {
        const float* __restrict__ hsrc = g_h[t & 1];
        float* __restrict__ hdst = g_h[(t & 1) ^ 1];

        // prefetch chunk 0 into registers
        float4 pf[8];
        #pragma unroll
        for (int q = 0; q < 8; ++q) {
            const int idx = tid + (q << 8);
            const int kk = idx >> 5, c4 = idx & 31;
            pf[q] = *(const float4*)&hsrc[kk * B_DIM + b0 + (c4 << 2)];
        }
        if (tid < BT) sx[tid] = x[(b0 + tid) * L_DIM + t];

        for (int kc = 0; kc < 8; ++kc) {
            __syncthreads();                       // previous chunk fully consumed
            #pragma unroll
            for (int q = 0; q < 8; ++q)
                ((float4*)hs)[tid + (q << 8)] = pf[q];
            if (kc < 7) {                           // prefetch next chunk (overlaps compute)
                #pragma unroll
                for (int q = 0; q < 8; ++q) {
                    const int idx = tid + (q << 8);
                    const int kk = idx >> 5, c4 = idx & 31;
                    pf[q] = *(const float4*)&hsrc[((kc + 1) * KCH + kk) * B_DIM + b0 + (c4 << 2)];
                }
            }
            __syncthreads();

            const float* wbase = Wsh + (kc * KCH) * WST + (rg << 3);
            const float* hbase = hs + cbase;
            #pragma unroll 4
            for (int kk = 0; kk < KCH; ++kk) {
                // weights: 8 consecutive rows -> 4 ready-made f32x2 pairs
                // (two broadcast LDS.128, zero packing MOVs)
                const u64* wp = (const u64*)(wbase + (kk << 6));
                const u64 w0 = wp[0], w1 = wp[1], w2 = wp[2], w3 = wp[3];
                // h: 4 scalars from one LDS.128, packed with 4 MOVs
                const float4 hv4 = *(const float4*)(hbase + (kk << 7));
                const u64 h0 = pack2(hv4.x), h1 = pack2(hv4.y);
                const u64 h2 = pack2(hv4.z), h3 = pack2(hv4.w);
                fma2(acc[0][0], w0, h0); fma2(acc[0][1], w0, h1);
                fma2(acc[0][2], w0, h2); fma2(acc[0][3], w0, h3);
                fma2(acc[1][0], w1, h0); fma2(acc[1][1], w1, h1);
                fma2(acc[1][2], w1, h2); fma2(acc[1][3], w1, h3);
                fma2(acc[2][0], w2, h0); fma2(acc[2][1], w2, h1);
                fma2(acc[2][2], w2, h2); fma2(acc[2][3], w2, h3);
                fma2(acc[3][0], w3, h0); fma2(acc[3][1], w3, h1);
                fma2(acc[3][2], w3, h2); fma2(acc[3][3], w3, h3);
            }
        }

        // ---- Gates + state update for owned (2 f-rows x 4 cols) ----
        const float xv[4] = {sx[cbase + 0], sx[cbase + 1], sx[cbase + 2], sx[cbase + 3]};
        #pragma unroll
        for (int fl2 = 0; fl2 < 2; ++fl2) {
            const int r0 = (rg << 3) + (fl2 << 2);
            const int fl = (rg << 1) + fl2;
            float4 hv;
            float* hvp = (float*)&hv;
            #pragma unroll
            for (int ci = 0; ci < 4; ++ci) {
                const float2 gi = unpack2(acc[(fl2 << 1) + 0][ci]);  // (g, i)
                const float2 fo = unpack2(acc[(fl2 << 1) + 1][ci]);  // (f, o)
                const float pg  = gi.x + swx[r0 + 0] * xv[ci] + bgc[ci];
                const float pi  = gi.y + swx[r0 + 1] * xv[ci] + bic[ci];
                const float pff = fo.x + swx[r0 + 2] * xv[ci] + bfc[ci];
                const float po  = fo.y + swx[r0 + 3] * xv[ci] + boc[ci];
                const float gg = tanh_acc(pg);
                const float si = sigm(pi);
                const float sf = sigm(pff);
                const float so = sigm(po);
                const float cn = gg * si + cst[(fl2 << 2) + ci] * sf;
                cst[(fl2 << 2) + ci] = cn;
                hvp[ci] = tanh_acc(cn) * so;
            }
            *(float4*)&hdst[(ftile * FT + fl) * B_DIM + b0 + cbase] = hv;
        }
        #pragma unroll
        for (int p = 0; p < 4; ++p)
            #pragma unroll
            for (int c = 0; c < 4; ++c) acc[p][c] = 0ull;
        gsync(&s_sense);
    }

    // ---- Projection: p = h^T @ w_ph + b_p ; final h is in g_h[0] (L even) ----
    {
        const float* __restrict__ hfin = g_h[0];
        const int c = tid & 127;
        const int brow = (bid << 2) + ((tid >> 7) << 1);  // block owns 4 batch rows
        float a0 = 0.0f, a1 = 0.0f;
        #pragma unroll 4
        for (int f = 0; f < F_DIM; ++f) {
            const float w = w_ph[f * C_DIM + c];
            a0 += hfin[f * B_DIM + brow] * w;
            a1 += hfin[f * B_DIM + brow + 1] * w;
        }
        const float bp = b_p[c];
        out[brow * C_DIM + c]       = a0 + bp;
        out[(brow + 1) * C_DIM + c] = a1 + bp;
    }
}

extern "C" void kernel_launch(void* const* d_in, const int* in_sizes, int n_in,
                              void* d_out, int out_size)
{
    (void)in_sizes; (void)n_in; (void)out_size;
    const float* x    = (const float*)d_in[0];
    const float* w_gx = (const float*)d_in[1];
    const float* w_gh = (const float*)d_in[2];
    const float* w_ix = (const float*)d_in[3];
    const float* w_ih = (const float*)d_in[4];
    const float* w_fx = (const float*)d_in[5];
    const float* w_fh = (const float*)d_in[6];
    const float* w_ox = (const float*)d_in[7];
    const float* w_oh = (const float*)d_in[8];
    const float* w_ph = (const float*)d_in[9];
    const float* b_g  = (const float*)d_in[10];
    const float* b_i  = (const float*)d_in[11];
    const float* b_f  = (const float*)d_in[12];
    const float* b_o  = (const float*)d_in[13];
    const float* b_p  = (const float*)d_in[14];
    float* out = (float*)d_out;

    const size_t smem_bytes = (size_t)(F_DIM * WST + KCH * BT + BT + 64) * sizeof(float);
    cudaFuncSetAttribute(lstm_persist_kernel,
                         cudaFuncAttributeMaxDynamicSharedMemorySize, (int)smem_bytes);

    lstm_persist_kernel<<<GRID_BLOCKS, THREADS, smem_bytes>>>(
        x, w_gx, w_gh, w_ix, w_ih, w_fx, w_fh, w_ox, w_oh, w_ph,
        b_g, b_i, b_f, b_o, b_p, out);
}